// round 1
// baseline (speedup 1.0000x reference)
#include <cuda_runtime.h>

// ---------------------------------------------------------------------------
// SNN forward: conv3x3(3->64)+IF+pool2 -> conv3x3(64->64)+IF+pool2 ->
//              FC(16384->4096)+IF -> FC(4096->10)+IF -> mean over T
// T=8, N=32, IMG=64. All fp32. f32x2 packed FMAs for throughput.
// ---------------------------------------------------------------------------

#define T_STEPS 8
#define NB      32

// Intermediates as device globals (no allocation allowed).
__device__ __align__(16) float g_pool1[T_STEPS * NB * 64 * 32 * 32]; // 64 MB spikes after stage 1
__device__ __align__(16) float g_pool2[T_STEPS * NB * 64 * 16 * 16]; // 16 MB spikes after stage 2
__device__ __align__(16) float g_fc1  [T_STEPS * NB * 4096];         // 4 MB FC1 pre-acts, then spikes in-place

// ----- f32x2 helpers (sm_100+ packed fp32 pipe: 2x FFMA throughput) -----
__device__ __forceinline__ unsigned long long pk2(float lo, float hi) {
    unsigned long long r;
    asm("mov.b64 %0, {%1, %2};" : "=l"(r) : "f"(lo), "f"(hi));
    return r;
}
__device__ __forceinline__ void upk2(unsigned long long v, float& lo, float& hi) {
    asm("mov.b64 {%0, %1}, %2;" : "=f"(lo), "=f"(hi) : "l"(v));
}
__device__ __forceinline__ void ffma2(unsigned long long& d, unsigned long long a, unsigned long long b) {
    asm("fma.rn.f32x2 %0, %1, %2, %3;" : "=l"(d) : "l"(a), "l"(b), "l"(d));
}

// IF neuron step: charge, fire (v >= 1), hard reset to 0.
__device__ __forceinline__ float ifstep(float& v, float add) {
    float nv = v + add;
    float s = (nv >= 1.0f) ? 1.0f : 0.0f;
    v = nv * (1.0f - s);
    return s;
}

// ---------------------------------------------------------------------------
// Kernel 1: conv1 (3->64, 3x3 pad1) + IF over T + maxpool2.
// Grid: (4 spatial tiles of 16x16 pooled px, 8 co-groups of 8, 32 n). 256 thr.
// Each thread: one 2x2 pool window for 8 output channels; IF state in regs.
// ---------------------------------------------------------------------------
__global__ void __launch_bounds__(256) conv1_if_pool(const float* __restrict__ x,
                                                     const float* __restrict__ w1) {
    __shared__ __align__(16) float xs[3 * 34 * 34];  // input tile (+halo), one t at a time
    __shared__ __align__(16) float ws[216];          // weights: [(ci*3+ky)*3+kx][co8]

    const int tile = blockIdx.x, cog = blockIdx.y, n = blockIdx.z;
    const int ty0 = (tile >> 1) * 16, tx0 = (tile & 1) * 16;
    const int tid = threadIdx.x;
    const int tyl = tid >> 4, txl = tid & 15;

    for (int idx = tid; idx < 216; idx += 256) {
        int co = idx & 7, r = idx >> 3;
        int kx = r % 3, ky = (r / 3) % 3, ci = r / 9;
        ws[idx] = w1[(cog * 8 + co) * 27 + ci * 9 + ky * 3 + kx];
    }

    float v[8][2][2];
#pragma unroll
    for (int c = 0; c < 8; c++) { v[c][0][0]=0.f; v[c][0][1]=0.f; v[c][1][0]=0.f; v[c][1][1]=0.f; }

    for (int t = 0; t < T_STEPS; t++) {
        __syncthreads();  // prior-iter reads done (also orders ws on first iter)
        const float* xb = x + (size_t)(t * NB + n) * 3 * 64 * 64;
        for (int idx = tid; idx < 3 * 34 * 34; idx += 256) {
            int ci = idx / 1156, rem = idx - ci * 1156;
            int r = rem / 34, c = rem - 34 * r;
            int gy = ty0 * 2 + r - 1, gx = tx0 * 2 + c - 1;
            float val = 0.f;
            if (gy >= 0 && gy < 64 && gx >= 0 && gx < 64) val = xb[ci * 4096 + gy * 64 + gx];
            xs[idx] = val;
        }
        __syncthreads();

        unsigned long long acc[4][2][2];
#pragma unroll
        for (int p = 0; p < 4; p++) { acc[p][0][0]=0ull; acc[p][0][1]=0ull; acc[p][1][0]=0ull; acc[p][1][1]=0ull; }

#pragma unroll
        for (int ci = 0; ci < 3; ci++) {
            float iv[4][4];
#pragma unroll
            for (int a = 0; a < 4; a++)
#pragma unroll
                for (int b = 0; b < 4; b++)
                    iv[a][b] = xs[ci * 1156 + (2 * tyl + a) * 34 + (2 * txl + b)];
#pragma unroll
            for (int ky = 0; ky < 3; ky++) {
#pragma unroll
                for (int kx = 0; kx < 3; kx++) {
                    unsigned long long pv00 = pk2(iv[ky][kx],     iv[ky][kx]);
                    unsigned long long pv01 = pk2(iv[ky][kx+1],   iv[ky][kx+1]);
                    unsigned long long pv10 = pk2(iv[ky+1][kx],   iv[ky+1][kx]);
                    unsigned long long pv11 = pk2(iv[ky+1][kx+1], iv[ky+1][kx+1]);
                    const float* wb = ws + (ci * 9 + ky * 3 + kx) * 8;
#pragma unroll
                    for (int p = 0; p < 4; p++) {
                        unsigned long long wp = *(const unsigned long long*)(wb + 2 * p);
                        ffma2(acc[p][0][0], wp, pv00);
                        ffma2(acc[p][0][1], wp, pv01);
                        ffma2(acc[p][1][0], wp, pv10);
                        ffma2(acc[p][1][1], wp, pv11);
                    }
                }
            }
        }

        // IF update + maxpool, write pooled spikes
        const size_t pbase = ((size_t)(t * NB + n) * 64 + cog * 8) * 1024
                           + (size_t)(ty0 + tyl) * 32 + (tx0 + txl);
#pragma unroll
        for (int p = 0; p < 4; p++) {
            float l00,h00,l01,h01,l10,h10,l11,h11;
            upk2(acc[p][0][0], l00, h00);
            upk2(acc[p][0][1], l01, h01);
            upk2(acc[p][1][0], l10, h10);
            upk2(acc[p][1][1], l11, h11);
            {
                const int co = 2 * p;
                float s0 = ifstep(v[co][0][0], l00);
                float s1 = ifstep(v[co][0][1], l01);
                float s2 = ifstep(v[co][1][0], l10);
                float s3 = ifstep(v[co][1][1], l11);
                g_pool1[pbase + (size_t)co * 1024] = fmaxf(fmaxf(s0, s1), fmaxf(s2, s3));
            }
            {
                const int co = 2 * p + 1;
                float s0 = ifstep(v[co][0][0], h00);
                float s1 = ifstep(v[co][0][1], h01);
                float s2 = ifstep(v[co][1][0], h10);
                float s3 = ifstep(v[co][1][1], h11);
                g_pool1[pbase + (size_t)co * 1024] = fmaxf(fmaxf(s0, s1), fmaxf(s2, s3));
            }
        }
    }
}

// ---------------------------------------------------------------------------
// Kernel 2: conv2 (64->64, 3x3 pad1 on 32x32) + IF over T + maxpool2.
// Grid: (4 row tiles of 8 conv rows, 2 co-groups of 32, 32 n). 256 threads.
// Thread = one 2x2 pool window x 8 output channels (4 f32x2 co-pairs).
// SMEM: input tile 64x10x34 f32 (87KB) + weights 64x9x32 (74KB).
// ---------------------------------------------------------------------------
#define C2_INS (64 * 10 * 34)
#define C2_WTS (64 * 9 * 32)

__global__ void __launch_bounds__(256) conv2_if_pool(const float* __restrict__ w2) {
    extern __shared__ float sm[];
    float* ins = sm;            // [ci][10][34]
    float* wsm = sm + C2_INS;   // [(ci*3+ky)*3+kx][co32]

    const int rt = blockIdx.x, cog = blockIdx.y, n = blockIdx.z;
    const int tid = threadIdx.x;
    const int wsid = tid & 63, wy = wsid >> 4, wx = wsid & 15;
    const int cs = tid >> 6;  // co slot: 8 channels each

    for (int idx = tid; idx < C2_WTS; idx += 256) {
        int co = idx & 31, r = idx >> 5;
        int kx = r % 3, ky = (r / 3) % 3, ci = r / 9;
        wsm[idx] = w2[(size_t)(cog * 32 + co) * 576 + ci * 9 + ky * 3 + kx];
    }

    float v[8][2][2];
#pragma unroll
    for (int c = 0; c < 8; c++) { v[c][0][0]=0.f; v[c][0][1]=0.f; v[c][1][0]=0.f; v[c][1][1]=0.f; }

    for (int t = 0; t < T_STEPS; t++) {
        __syncthreads();
        const float* pb = g_pool1 + (size_t)(t * NB + n) * 64 * 1024;
        for (int idx = tid; idx < C2_INS; idx += 256) {
            int ci = idx / 340, rem = idx - ci * 340;
            int r = rem / 34, c = rem - 34 * r;
            int gy = rt * 8 + r - 1, gx = c - 1;
            float val = 0.f;
            if (gy >= 0 && gy < 32 && gx >= 0 && gx < 32) val = pb[ci * 1024 + gy * 32 + gx];
            ins[idx] = val;
        }
        __syncthreads();

        unsigned long long acc[4][2][2];
#pragma unroll
        for (int p = 0; p < 4; p++) { acc[p][0][0]=0ull; acc[p][0][1]=0ull; acc[p][1][0]=0ull; acc[p][1][1]=0ull; }

        for (int ci = 0; ci < 64; ci++) {
            const float* ip = ins + ci * 340 + (2 * wy) * 34 + 2 * wx;
            const float* wc = wsm + ci * 9 * 32 + cs * 8;
#pragma unroll
            for (int ky = 0; ky < 3; ky++) {
#pragma unroll
                for (int kx = 0; kx < 3; kx++) {
                    float i00 = ip[ky * 34 + kx];
                    float i01 = ip[ky * 34 + kx + 1];
                    float i10 = ip[(ky + 1) * 34 + kx];
                    float i11 = ip[(ky + 1) * 34 + kx + 1];
                    unsigned long long pv00 = pk2(i00, i00);
                    unsigned long long pv01 = pk2(i01, i01);
                    unsigned long long pv10 = pk2(i10, i10);
                    unsigned long long pv11 = pk2(i11, i11);
                    const float* wb = wc + (ky * 3 + kx) * 32;
#pragma unroll
                    for (int p = 0; p < 4; p++) {
                        unsigned long long wp = *(const unsigned long long*)(wb + 2 * p);
                        ffma2(acc[p][0][0], wp, pv00);
                        ffma2(acc[p][0][1], wp, pv01);
                        ffma2(acc[p][1][0], wp, pv10);
                        ffma2(acc[p][1][1], wp, pv11);
                    }
                }
            }
        }

        const int pooly = rt * 4 + wy;
        const size_t obase = ((size_t)(t * NB + n) * 64 + cog * 32 + cs * 8) * 256
                           + (size_t)pooly * 16 + wx;
#pragma unroll
        for (int p = 0; p < 4; p++) {
            float l00,h00,l01,h01,l10,h10,l11,h11;
            upk2(acc[p][0][0], l00, h00);
            upk2(acc[p][0][1], l01, h01);
            upk2(acc[p][1][0], l10, h10);
            upk2(acc[p][1][1], l11, h11);
            {
                const int co = 2 * p;
                float s0 = ifstep(v[co][0][0], l00);
                float s1 = ifstep(v[co][0][1], l01);
                float s2 = ifstep(v[co][1][0], l10);
                float s3 = ifstep(v[co][1][1], l11);
                g_pool2[obase + (size_t)co * 256] = fmaxf(fmaxf(s0, s1), fmaxf(s2, s3));
            }
            {
                const int co = 2 * p + 1;
                float s0 = ifstep(v[co][0][0], h00);
                float s1 = ifstep(v[co][0][1], h01);
                float s2 = ifstep(v[co][1][0], h10);
                float s3 = ifstep(v[co][1][1], h11);
                g_pool2[obase + (size_t)co * 256] = fmaxf(fmaxf(s0, s1), fmaxf(s2, s3));
            }
        }
    }
}

// ---------------------------------------------------------------------------
// Kernel 3: FC1 GEMM. C[256,4096] = S[256,16384] * fc1[4096,16384]^T (fp32).
// Tile 64(M) x 128(N), Kb=16. 256 threads, microtile 8m x 4n via f32x2 pairs.
// ---------------------------------------------------------------------------
#define KB 16
__global__ void __launch_bounds__(256) fc1_gemm(const float* __restrict__ W) {
    __shared__ __align__(16) float As[KB * 64];   // [k][m]
    __shared__ __align__(16) float Bs[KB * 132];  // [k][n] padded

    const int n0 = blockIdx.x * 128, m0 = blockIdx.y * 64;
    const int tid = threadIdx.x;
    const int mt = tid >> 5, nt = tid & 31;

    unsigned long long acc[4][4];
#pragma unroll
    for (int i = 0; i < 4; i++)
#pragma unroll
        for (int j = 0; j < 4; j++) acc[i][j] = 0ull;

    const float* A = g_pool2;  // [256][16384] row-major (c*256+h*16+w matches flatten)

    for (int k0 = 0; k0 < 16384; k0 += KB) {
        {
            int m = tid >> 2, q = tid & 3;
            float4 va = *(const float4*)(A + (size_t)(m0 + m) * 16384 + k0 + q * 4);
            As[(q * 4 + 0) * 64 + m] = va.x;
            As[(q * 4 + 1) * 64 + m] = va.y;
            As[(q * 4 + 2) * 64 + m] = va.z;
            As[(q * 4 + 3) * 64 + m] = va.w;
        }
#pragma unroll
        for (int s = 0; s < 2; s++) {
            int idx = tid + s * 256;
            int jr = idx >> 2, q = idx & 3;
            float4 vb = *(const float4*)(W + (size_t)(n0 + jr) * 16384 + k0 + q * 4);
            Bs[(q * 4 + 0) * 132 + jr] = vb.x;
            Bs[(q * 4 + 1) * 132 + jr] = vb.y;
            Bs[(q * 4 + 2) * 132 + jr] = vb.z;
            Bs[(q * 4 + 3) * 132 + jr] = vb.w;
        }
        __syncthreads();

#pragma unroll
        for (int kk = 0; kk < KB; kk++) {
            const float* ar = As + kk * 64 + mt * 8;
            unsigned long long a0 = *(const unsigned long long*)(ar + 0);
            unsigned long long a1 = *(const unsigned long long*)(ar + 2);
            unsigned long long a2 = *(const unsigned long long*)(ar + 4);
            unsigned long long a3 = *(const unsigned long long*)(ar + 6);
            float4 b4 = *(const float4*)(Bs + kk * 132 + nt * 4);
            unsigned long long b0 = pk2(b4.x, b4.x);
            unsigned long long b1 = pk2(b4.y, b4.y);
            unsigned long long b2 = pk2(b4.z, b4.z);
            unsigned long long b3 = pk2(b4.w, b4.w);
            ffma2(acc[0][0], a0, b0); ffma2(acc[0][1], a0, b1); ffma2(acc[0][2], a0, b2); ffma2(acc[0][3], a0, b3);
            ffma2(acc[1][0], a1, b0); ffma2(acc[1][1], a1, b1); ffma2(acc[1][2], a1, b2); ffma2(acc[1][3], a1, b3);
            ffma2(acc[2][0], a2, b0); ffma2(acc[2][1], a2, b1); ffma2(acc[2][2], a2, b2); ffma2(acc[2][3], a2, b3);
            ffma2(acc[3][0], a3, b0); ffma2(acc[3][1], a3, b1); ffma2(acc[3][2], a3, b2); ffma2(acc[3][3], a3, b3);
        }
        __syncthreads();
    }

#pragma unroll
    for (int i = 0; i < 4; i++) {
#pragma unroll
        for (int j = 0; j < 4; j++) {
            float lo, hi;
            upk2(acc[i][j], lo, hi);
            int m = m0 + mt * 8 + 2 * i;
            int nn = n0 + nt * 4 + j;
            g_fc1[(size_t)m * 4096 + nn]       = lo;
            g_fc1[(size_t)(m + 1) * 4096 + nn] = hi;
        }
    }
}

// ---------------------------------------------------------------------------
// Kernel 4: IF over T on FC1 pre-activations, in place (pre -> spikes).
// ---------------------------------------------------------------------------
__global__ void fc1_if() {
    int g = blockIdx.x * blockDim.x + threadIdx.x;  // 32*4096 threads
    int n = g >> 12, o = g & 4095;
    float v = 0.f;
#pragma unroll
    for (int t = 0; t < T_STEPS; t++) {
        size_t idx = (size_t)(t * NB + n) * 4096 + o;
        float s = ifstep(v, g_fc1[idx]);
        g_fc1[idx] = s;
    }
}

// ---------------------------------------------------------------------------
// Kernel 5: FC2 (4096->10) + IF over T + mean -> out[32,10].
// One CTA (128 thr) per (n, o); block-reduce dot per t; state on thread 0.
// ---------------------------------------------------------------------------
__global__ void fc2_head(const float* __restrict__ W2, float* __restrict__ out) {
    const int n = blockIdx.x / 10, o = blockIdx.x % 10;
    const int tid = threadIdx.x;
    const float* wrow = W2 + (size_t)o * 4096;
    __shared__ float red[4];
    float v = 0.f, rate = 0.f;

    for (int t = 0; t < T_STEPS; t++) {
        const float* srow = g_fc1 + (size_t)(t * NB + n) * 4096;
        float s = 0.f;
        for (int i = tid; i < 4096; i += 128) s += srow[i] * wrow[i];
#pragma unroll
        for (int off = 16; off; off >>= 1) s += __shfl_down_sync(0xffffffffu, s, off);
        if ((tid & 31) == 0) red[tid >> 5] = s;
        __syncthreads();
        if (tid == 0) {
            float tot = red[0] + red[1] + red[2] + red[3];
            rate += ifstep(v, tot);
        }
        __syncthreads();
    }
    if (tid == 0) out[n * 10 + o] = rate * 0.125f;
}

// ---------------------------------------------------------------------------
extern "C" void kernel_launch(void* const* d_in, const int* in_sizes, int n_in,
                              void* d_out, int out_size) {
    const float* x   = (const float*)d_in[0];
    const float* w1  = (const float*)d_in[1];
    const float* w2  = (const float*)d_in[2];
    const float* fc1 = (const float*)d_in[3];
    const float* fc2 = (const float*)d_in[4];
    float* out = (float*)d_out;

    conv1_if_pool<<<dim3(4, 8, 32), 256>>>(x, w1);

    const int smem2 = (C2_INS + C2_WTS) * (int)sizeof(float);  // 160768 B
    cudaFuncSetAttribute(conv2_if_pool, cudaFuncAttributeMaxDynamicSharedMemorySize, smem2);
    conv2_if_pool<<<dim3(4, 2, 32), 256, smem2>>>(w2);

    fc1_gemm<<<dim3(32, 4), 256>>>(fc1);
    fc1_if<<<512, 256>>>();
    fc2_head<<<320, 128>>>(fc2, out);
}

// round 3
// speedup vs baseline: 1.8404x; 1.8404x over previous
#include <cuda_runtime.h>
#include <cuda_bf16.h>

#define T_STEPS 8
#define NB      32

// Intermediates (no allocation allowed).
__device__ __align__(16) float         g_pool1[T_STEPS * NB * 64 * 32 * 32]; // 64 MB stage-1 spikes (fp32)
__device__ __align__(16) __nv_bfloat16 g_act2 [T_STEPS * NB * 16384];        // 8 MB stage-2 spikes (bf16, exact 0/1)
__device__ __align__(16) float         g_fc1p [2 * 256 * 4096];              // 8 MB FC1 K-split partials
__device__ __align__(16) float         g_fc1  [T_STEPS * NB * 4096];         // 4 MB FC1 spikes

// ----- f32x2 packed helpers -----
__device__ __forceinline__ unsigned long long pk2(float lo, float hi) {
    unsigned long long r;
    asm("mov.b64 %0, {%1, %2};" : "=l"(r) : "f"(lo), "f"(hi));
    return r;
}
__device__ __forceinline__ void upk2(unsigned long long v, float& lo, float& hi) {
    asm("mov.b64 {%0, %1}, %2;" : "=f"(lo), "=f"(hi) : "l"(v));
}
__device__ __forceinline__ void ffma2(unsigned long long& d, unsigned long long a, unsigned long long b) {
    asm("fma.rn.f32x2 %0, %1, %2, %3;" : "=l"(d) : "l"(a), "l"(b), "l"(d));
}

__device__ __forceinline__ float ifstep(float& v, float add) {
    float nv = v + add;
    float s = (nv >= 1.0f) ? 1.0f : 0.0f;
    v = nv * (1.0f - s);
    return s;
}

__device__ __forceinline__ unsigned smem_u32(const void* p) {
    unsigned a;
    asm("{ .reg .u64 t; cvta.to.shared.u64 t, %1; cvt.u32.u64 %0, t; }" : "=r"(a) : "l"(p));
    return a;
}

// ---------------------------------------------------------------------------
// Kernel 1: conv1 (3->64) + IF + pool  (unchanged, passing since R1)
// ---------------------------------------------------------------------------
__global__ void __launch_bounds__(256) conv1_if_pool(const float* __restrict__ x,
                                                     const float* __restrict__ w1) {
    __shared__ __align__(16) float xs[3 * 34 * 34];
    __shared__ __align__(16) float ws[216];

    const int tile = blockIdx.x, cog = blockIdx.y, n = blockIdx.z;
    const int ty0 = (tile >> 1) * 16, tx0 = (tile & 1) * 16;
    const int tid = threadIdx.x;
    const int tyl = tid >> 4, txl = tid & 15;

    for (int idx = tid; idx < 216; idx += 256) {
        int co = idx & 7, r = idx >> 3;
        int kx = r % 3, ky = (r / 3) % 3, ci = r / 9;
        ws[idx] = w1[(cog * 8 + co) * 27 + ci * 9 + ky * 3 + kx];
    }

    float v[8][2][2];
#pragma unroll
    for (int c = 0; c < 8; c++) { v[c][0][0]=0.f; v[c][0][1]=0.f; v[c][1][0]=0.f; v[c][1][1]=0.f; }

    for (int t = 0; t < T_STEPS; t++) {
        __syncthreads();
        const float* xb = x + (size_t)(t * NB + n) * 3 * 64 * 64;
        for (int idx = tid; idx < 3 * 34 * 34; idx += 256) {
            int ci = idx / 1156, rem = idx - ci * 1156;
            int r = rem / 34, c = rem - 34 * r;
            int gy = ty0 * 2 + r - 1, gx = tx0 * 2 + c - 1;
            float val = 0.f;
            if (gy >= 0 && gy < 64 && gx >= 0 && gx < 64) val = xb[ci * 4096 + gy * 64 + gx];
            xs[idx] = val;
        }
        __syncthreads();

        unsigned long long acc[4][2][2];
#pragma unroll
        for (int p = 0; p < 4; p++) { acc[p][0][0]=0ull; acc[p][0][1]=0ull; acc[p][1][0]=0ull; acc[p][1][1]=0ull; }

#pragma unroll
        for (int ci = 0; ci < 3; ci++) {
            float iv[4][4];
#pragma unroll
            for (int a = 0; a < 4; a++)
#pragma unroll
                for (int b = 0; b < 4; b++)
                    iv[a][b] = xs[ci * 1156 + (2 * tyl + a) * 34 + (2 * txl + b)];
#pragma unroll
            for (int ky = 0; ky < 3; ky++) {
#pragma unroll
                for (int kx = 0; kx < 3; kx++) {
                    unsigned long long pv00 = pk2(iv[ky][kx],     iv[ky][kx]);
                    unsigned long long pv01 = pk2(iv[ky][kx+1],   iv[ky][kx+1]);
                    unsigned long long pv10 = pk2(iv[ky+1][kx],   iv[ky+1][kx]);
                    unsigned long long pv11 = pk2(iv[ky+1][kx+1], iv[ky+1][kx+1]);
                    const float* wb = ws + (ci * 9 + ky * 3 + kx) * 8;
#pragma unroll
                    for (int p = 0; p < 4; p++) {
                        unsigned long long wp = *(const unsigned long long*)(wb + 2 * p);
                        ffma2(acc[p][0][0], wp, pv00);
                        ffma2(acc[p][0][1], wp, pv01);
                        ffma2(acc[p][1][0], wp, pv10);
                        ffma2(acc[p][1][1], wp, pv11);
                    }
                }
            }
        }

        const size_t pbase = ((size_t)(t * NB + n) * 64 + cog * 8) * 1024
                           + (size_t)(ty0 + tyl) * 32 + (tx0 + txl);
#pragma unroll
        for (int p = 0; p < 4; p++) {
            float l00,h00,l01,h01,l10,h10,l11,h11;
            upk2(acc[p][0][0], l00, h00);
            upk2(acc[p][0][1], l01, h01);
            upk2(acc[p][1][0], l10, h10);
            upk2(acc[p][1][1], l11, h11);
            {
                const int co = 2 * p;
                float s0 = ifstep(v[co][0][0], l00);
                float s1 = ifstep(v[co][0][1], l01);
                float s2 = ifstep(v[co][1][0], l10);
                float s3 = ifstep(v[co][1][1], l11);
                g_pool1[pbase + (size_t)co * 1024] = fmaxf(fmaxf(s0, s1), fmaxf(s2, s3));
            }
            {
                const int co = 2 * p + 1;
                float s0 = ifstep(v[co][0][0], h00);
                float s1 = ifstep(v[co][0][1], h01);
                float s2 = ifstep(v[co][1][0], h10);
                float s3 = ifstep(v[co][1][1], h11);
                g_pool1[pbase + (size_t)co * 1024] = fmaxf(fmaxf(s0, s1), fmaxf(s2, s3));
            }
        }
    }
}

// ---------------------------------------------------------------------------
// Kernel 2: conv2 (64->64) + IF + pool -> bf16 spikes (exact 0/1)
// ---------------------------------------------------------------------------
#define C2_INS (64 * 10 * 34)
#define C2_WTS (64 * 9 * 32)

__global__ void __launch_bounds__(256) conv2_if_pool(const float* __restrict__ w2) {
    extern __shared__ float sm[];
    float* ins = sm;
    float* wsm = sm + C2_INS;

    const int rt = blockIdx.x, cog = blockIdx.y, n = blockIdx.z;
    const int tid = threadIdx.x;
    const int wsid = tid & 63, wy = wsid >> 4, wx = wsid & 15;
    const int cs = tid >> 6;

    for (int idx = tid; idx < C2_WTS; idx += 256) {
        int co = idx & 31, r = idx >> 5;
        int kx = r % 3, ky = (r / 3) % 3, ci = r / 9;
        wsm[idx] = w2[(size_t)(cog * 32 + co) * 576 + ci * 9 + ky * 3 + kx];
    }

    float v[8][2][2];
#pragma unroll
    for (int c = 0; c < 8; c++) { v[c][0][0]=0.f; v[c][0][1]=0.f; v[c][1][0]=0.f; v[c][1][1]=0.f; }

    for (int t = 0; t < T_STEPS; t++) {
        __syncthreads();
        const float* pb = g_pool1 + (size_t)(t * NB + n) * 64 * 1024;
        for (int idx = tid; idx < C2_INS; idx += 256) {
            int ci = idx / 340, rem = idx - ci * 340;
            int r = rem / 34, c = rem - 34 * r;
            int gy = rt * 8 + r - 1, gx = c - 1;
            float val = 0.f;
            if (gy >= 0 && gy < 32 && gx >= 0 && gx < 32) val = pb[ci * 1024 + gy * 32 + gx];
            ins[idx] = val;
        }
        __syncthreads();

        unsigned long long acc[4][2][2];
#pragma unroll
        for (int p = 0; p < 4; p++) { acc[p][0][0]=0ull; acc[p][0][1]=0ull; acc[p][1][0]=0ull; acc[p][1][1]=0ull; }

        for (int ci = 0; ci < 64; ci++) {
            const float* ip = ins + ci * 340 + (2 * wy) * 34 + 2 * wx;
            const float* wc = wsm + ci * 9 * 32 + cs * 8;
#pragma unroll
            for (int ky = 0; ky < 3; ky++) {
#pragma unroll
                for (int kx = 0; kx < 3; kx++) {
                    float i00 = ip[ky * 34 + kx];
                    float i01 = ip[ky * 34 + kx + 1];
                    float i10 = ip[(ky + 1) * 34 + kx];
                    float i11 = ip[(ky + 1) * 34 + kx + 1];
                    unsigned long long pv00 = pk2(i00, i00);
                    unsigned long long pv01 = pk2(i01, i01);
                    unsigned long long pv10 = pk2(i10, i10);
                    unsigned long long pv11 = pk2(i11, i11);
                    const float* wb = wc + (ky * 3 + kx) * 32;
#pragma unroll
                    for (int p = 0; p < 4; p++) {
                        unsigned long long wp = *(const unsigned long long*)(wb + 2 * p);
                        ffma2(acc[p][0][0], wp, pv00);
                        ffma2(acc[p][0][1], wp, pv01);
                        ffma2(acc[p][1][0], wp, pv10);
                        ffma2(acc[p][1][1], wp, pv11);
                    }
                }
            }
        }

        const int pooly = rt * 4 + wy;
        const size_t obase = ((size_t)(t * NB + n) * 64 + cog * 32 + cs * 8) * 256
                           + (size_t)pooly * 16 + wx;
#pragma unroll
        for (int p = 0; p < 4; p++) {
            float l00,h00,l01,h01,l10,h10,l11,h11;
            upk2(acc[p][0][0], l00, h00);
            upk2(acc[p][0][1], l01, h01);
            upk2(acc[p][1][0], l10, h10);
            upk2(acc[p][1][1], l11, h11);
            {
                const int co = 2 * p;
                float s0 = ifstep(v[co][0][0], l00);
                float s1 = ifstep(v[co][0][1], l01);
                float s2 = ifstep(v[co][1][0], l10);
                float s3 = ifstep(v[co][1][1], l11);
                g_act2[obase + (size_t)co * 256] = __float2bfloat16(fmaxf(fmaxf(s0, s1), fmaxf(s2, s3)));
            }
            {
                const int co = 2 * p + 1;
                float s0 = ifstep(v[co][0][0], h00);
                float s1 = ifstep(v[co][0][1], h01);
                float s2 = ifstep(v[co][1][0], h10);
                float s3 = ifstep(v[co][1][1], h11);
                g_act2[obase + (size_t)co * 256] = __float2bfloat16(fmaxf(fmaxf(s0, s1), fmaxf(s2, s3)));
            }
        }
    }
}

// ---------------------------------------------------------------------------
// Kernel 3: FC1 via mma.sync bf16 (legacy HMMA path — family-generic PTX),
// exact 3-way bf16 weight split, K-split x2 into partial buffers.
//   C[256,4096] = A[256,16384] (binary spikes, bf16) @ W[4096,16384]^T (fp32)
// CTA: 256 thr / 8 warps, tile M=256 x N=64, KB=32, 2-stage SMEM ring.
// Warp tile 64x32 (warps 4m x 2n); per k-step: 4 A ldmatrix, per split 2 B
// ldmatrix + 16 mma. SMEM rows padded to 80B -> conflict-free ldmatrix.
// ---------------------------------------------------------------------------
#define F_ITERS 256            // 8192 / 32 per K-half
#define FSTAGE  35840          // A: 256*80 + W: 3*64*80
#define FA_OFF  0
#define FW_OFF  20480
#define FW_SPL  5120
#define F_SMEM  (2 * FSTAGE)   // 71680 B

#define LDSM4(r0, r1, r2, r3, a) \
    asm volatile("ldmatrix.sync.aligned.m8n8.x4.shared.b16 {%0,%1,%2,%3}, [%4];" \
                 : "=r"(r0), "=r"(r1), "=r"(r2), "=r"(r3) : "r"(a))

#define MMA16816(d, a, b0, b1) \
    asm volatile("mma.sync.aligned.m16n8k16.row.col.f32.bf16.bf16.f32 " \
                 "{%0,%1,%2,%3}, {%4,%5,%6,%7}, {%8,%9}, {%0,%1,%2,%3};" \
                 : "+f"((d)[0]), "+f"((d)[1]), "+f"((d)[2]), "+f"((d)[3]) \
                 : "r"((a)[0]), "r"((a)[1]), "r"((a)[2]), "r"((a)[3]), "r"(b0), "r"(b1))

__device__ __forceinline__ void f_ldg(const float* __restrict__ W, int n0, int k0,
                                      int tid, uint4 aR[4], float4 wR[2]) {
#pragma unroll
    for (int j = 0; j < 4; j++) {
        int c = tid + j * 256, row = c >> 2, seg = c & 3;
        aR[j] = *(const uint4*)(g_act2 + (size_t)row * 16384 + k0 + seg * 8);
    }
#pragma unroll
    for (int j = 0; j < 2; j++) {
        int c = tid + j * 256, row = c >> 3, seg = c & 7;
        wR[j] = *(const float4*)(W + (size_t)(n0 + row) * 16384 + k0 + seg * 4);
    }
}

__device__ __forceinline__ void f_sts(char* sm, int p, int tid,
                                      const uint4 aR[4], const float4 wR[2]) {
    char* base = sm + p * FSTAGE;
#pragma unroll
    for (int j = 0; j < 4; j++) {
        int c = tid + j * 256, row = c >> 2, seg = c & 3;
        *(uint4*)(base + FA_OFF + row * 80 + seg * 16) = aR[j];
    }
#pragma unroll
    for (int j = 0; j < 2; j++) {
        int c = tid + j * 256, row = c >> 3, seg = c & 7;
        float vv[4] = {wR[j].x, wR[j].y, wR[j].z, wR[j].w};
        unsigned h1[4], h2[4], h3[4];
#pragma unroll
        for (int q = 0; q < 4; q++) {
            float v = vv[q];
            __nv_bfloat16 b1 = __float2bfloat16(v);
            float r1 = v - __bfloat162float(b1);
            __nv_bfloat16 b2 = __float2bfloat16(r1);
            float r2 = r1 - __bfloat162float(b2);
            __nv_bfloat16 b3 = __float2bfloat16(r2);
            h1[q] = __bfloat16_as_ushort(b1);
            h2[q] = __bfloat16_as_ushort(b2);
            h3[q] = __bfloat16_as_ushort(b3);
        }
        uint2 p1 = make_uint2(h1[0] | (h1[1] << 16), h1[2] | (h1[3] << 16));
        uint2 p2 = make_uint2(h2[0] | (h2[1] << 16), h2[2] | (h2[3] << 16));
        uint2 p3 = make_uint2(h3[0] | (h3[1] << 16), h3[2] | (h3[3] << 16));
        unsigned off = row * 80 + seg * 8;
        *(uint2*)(base + FW_OFF + 0 * FW_SPL + off) = p1;
        *(uint2*)(base + FW_OFF + 1 * FW_SPL + off) = p2;
        *(uint2*)(base + FW_OFF + 2 * FW_SPL + off) = p3;
    }
}

__global__ void __launch_bounds__(256, 1) fc1_hmma(const float* __restrict__ W) {
    extern __shared__ __align__(16) char smg[];
    const unsigned smb = smem_u32(smg);
    const int tid = threadIdx.x;
    const int wid = tid >> 5, lane = tid & 31;
    const int wm = wid >> 1, wn = wid & 1;
    const int n0 = blockIdx.x * 64;
    const int kbase = blockIdx.y * 8192;

    float acc[4][4][4];
#pragma unroll
    for (int mt = 0; mt < 4; mt++)
#pragma unroll
        for (int nt = 0; nt < 4; nt++)
#pragma unroll
            for (int q = 0; q < 4; q++) acc[mt][nt][q] = 0.f;

    // ldmatrix per-lane addressing: group g = lane>>3 -> row (g&1)*8 + (lane&7),
    // 16B k-chunk = g>>1.
    const unsigned lrow = ((lane >> 3) & 1) * 8 + (lane & 7);
    const unsigned lk16 = (lane >> 4) * 16;
    const unsigned a_l = (wm * 64 + lrow) * 80 + lk16;
    const unsigned b_l = (wn * 32 + lrow) * 80 + lk16;

    uint4 aR[4];
    float4 wR[2];

    f_ldg(W, n0, kbase, tid, aR, wR);
    f_sts(smg, 0, tid, aR, wR);
    __syncthreads();

    for (int i = 0; i < F_ITERS; i++) {
        const int p = i & 1;
        const bool more = (i + 1 < F_ITERS);
        if (more) f_ldg(W, n0, kbase + (i + 1) * 32, tid, aR, wR);

        const unsigned ab = smb + p * FSTAGE + FA_OFF + a_l;
        const unsigned bb = smb + p * FSTAGE + FW_OFF + b_l;
#pragma unroll
        for (int ks = 0; ks < 2; ks++) {
            unsigned af[4][4];
#pragma unroll
            for (int mt = 0; mt < 4; mt++)
                LDSM4(af[mt][0], af[mt][1], af[mt][2], af[mt][3],
                      ab + mt * (16 * 80) + ks * 32);
#pragma unroll
            for (int s = 0; s < 3; s++) {
                unsigned q0, q1, q2, q3, u0, u1, u2, u3;
                LDSM4(q0, q1, q2, q3, bb + s * FW_SPL + ks * 32);            // n-tiles 0,1
                LDSM4(u0, u1, u2, u3, bb + s * FW_SPL + 16 * 80 + ks * 32);  // n-tiles 2,3
#pragma unroll
                for (int mt = 0; mt < 4; mt++) {
                    MMA16816(acc[mt][0], af[mt], q0, q2);
                    MMA16816(acc[mt][1], af[mt], q1, q3);
                    MMA16816(acc[mt][2], af[mt], u0, u2);
                    MMA16816(acc[mt][3], af[mt], u1, u3);
                }
            }
        }
        __syncthreads();
        if (more) {
            f_sts(smg, p ^ 1, tid, aR, wR);
            __syncthreads();
        }
    }

    float* dst = g_fc1p + (size_t)blockIdx.y * (256 * 4096);
#pragma unroll
    for (int mt = 0; mt < 4; mt++) {
        int m = wm * 64 + mt * 16 + (lane >> 2);
#pragma unroll
        for (int nt = 0; nt < 4; nt++) {
            int col = n0 + wn * 32 + nt * 8 + 2 * (lane & 3);
            *(float2*)(dst + (size_t)m * 4096 + col)       = make_float2(acc[mt][nt][0], acc[mt][nt][1]);
            *(float2*)(dst + (size_t)(m + 8) * 4096 + col) = make_float2(acc[mt][nt][2], acc[mt][nt][3]);
        }
    }
}

// ---------------------------------------------------------------------------
// Kernel 4: sum K-split partials + IF over T -> spikes in g_fc1.
// ---------------------------------------------------------------------------
__global__ void fc1_if() {
    int g = blockIdx.x * blockDim.x + threadIdx.x;
    int n = g >> 12, o = g & 4095;
    float v = 0.f;
#pragma unroll
    for (int t = 0; t < T_STEPS; t++) {
        size_t idx = (size_t)(t * NB + n) * 4096 + o;
        float pre = g_fc1p[idx] + g_fc1p[256 * 4096 + idx];
        g_fc1[idx] = ifstep(v, pre);
    }
}

// ---------------------------------------------------------------------------
// Kernel 5: FC2 + IF + rate.
// ---------------------------------------------------------------------------
__global__ void fc2_head(const float* __restrict__ W2, float* __restrict__ out) {
    const int n = blockIdx.x / 10, o = blockIdx.x % 10;
    const int tid = threadIdx.x;
    const float* wrow = W2 + (size_t)o * 4096;
    __shared__ float red[4];
    float v = 0.f, rate = 0.f;

    for (int t = 0; t < T_STEPS; t++) {
        const float* srow = g_fc1 + (size_t)(t * NB + n) * 4096;
        float s = 0.f;
        for (int i = tid; i < 4096; i += 128) s += srow[i] * wrow[i];
#pragma unroll
        for (int off = 16; off; off >>= 1) s += __shfl_down_sync(0xffffffffu, s, off);
        if ((tid & 31) == 0) red[tid >> 5] = s;
        __syncthreads();
        if (tid == 0) {
            float tot = red[0] + red[1] + red[2] + red[3];
            rate += ifstep(v, tot);
        }
        __syncthreads();
    }
    if (tid == 0) out[n * 10 + o] = rate * 0.125f;
}

// ---------------------------------------------------------------------------
extern "C" void kernel_launch(void* const* d_in, const int* in_sizes, int n_in,
                              void* d_out, int out_size) {
    const float* x   = (const float*)d_in[0];
    const float* w1  = (const float*)d_in[1];
    const float* w2  = (const float*)d_in[2];
    const float* fc1 = (const float*)d_in[3];
    const float* fc2 = (const float*)d_in[4];
    float* out = (float*)d_out;

    conv1_if_pool<<<dim3(4, 8, 32), 256>>>(x, w1);

    const int smem2 = (C2_INS + C2_WTS) * (int)sizeof(float);
    cudaFuncSetAttribute(conv2_if_pool, cudaFuncAttributeMaxDynamicSharedMemorySize, smem2);
    conv2_if_pool<<<dim3(4, 2, 32), 256, smem2>>>(w2);

    cudaFuncSetAttribute(fc1_hmma, cudaFuncAttributeMaxDynamicSharedMemorySize, F_SMEM);
    fc1_hmma<<<dim3(64, 2), 256, F_SMEM>>>(fc1);

    fc1_if<<<512, 256>>>();
    fc2_head<<<320, 128>>>(fc2, out);
}